// round 12
// baseline (speedup 1.0000x reference)
#include <cuda_runtime.h>
#include <cuda_fp16.h>
#include <math.h>
#include <stdint.h>

#define B_ 4
#define T_ 2048
#define C_ 1024
#define F_ 4096
#define MROWS (B_*T_)   // 8192

// ---------------- scratch (device globals; no allocation allowed) ----------
__device__ __align__(128) float  g_x[(size_t)MROWS*C_];        // residual (fp32)
__device__ __align__(128) __half g_h[(size_t)MROWS*C_];        // LN out
__device__ __align__(128) __half g_qkv[(size_t)MROWS*3*C_];
__device__ __align__(128) __half g_att[(size_t)B_*T_*T_];      // scores -> probs (in place)
__device__ __align__(128) __half g_ao[(size_t)MROWS*C_];
__device__ __align__(128) __half g_vt[(size_t)B_*C_*T_];       // v^T per batch
__device__ __align__(128) __half g_ff[(size_t)MROWS*F_];
// fp16 weights
__device__ __align__(128) __half g_wqkv[(size_t)8*3*C_*C_];
__device__ __align__(128) __half g_wout[(size_t)8*C_*C_];
__device__ __align__(128) __half g_wff0[(size_t)8*F_*C_];
__device__ __align__(128) __half g_wff3[(size_t)8*C_*F_];

// ================= base-target PTX helpers =================
__device__ __forceinline__ uint32_t smem_u32(const void* p) {
    uint32_t a;
    asm("{ .reg .u64 t; cvta.to.shared.u64 t, %1; cvt.u32.u64 %0, t; }" : "=r"(a) : "l"(p));
    return a;
}
__device__ __forceinline__ void cp_async16(uint32_t saddr, const void* gptr) {
    asm volatile("cp.async.cg.shared.global [%0], [%1], 16;" :: "r"(saddr), "l"(gptr) : "memory");
}
#define CP_COMMIT()  asm volatile("cp.async.commit_group;" ::: "memory")
#define CP_WAIT(n)   asm volatile("cp.async.wait_group %0;" :: "n"(n) : "memory")

__device__ __forceinline__ void ldsm4(uint32_t& r0, uint32_t& r1, uint32_t& r2, uint32_t& r3,
                                      uint32_t addr) {
    asm volatile("ldmatrix.sync.aligned.m8n8.x4.shared.b16 {%0,%1,%2,%3}, [%4];"
                 : "=r"(r0), "=r"(r1), "=r"(r2), "=r"(r3) : "r"(addr));
}
__device__ __forceinline__ void mma_f16(float* d, const uint32_t* a, const uint32_t* b) {
    asm volatile("mma.sync.aligned.m16n8k16.row.col.f32.f16.f16.f32 "
                 "{%0,%1,%2,%3}, {%4,%5,%6,%7}, {%8,%9}, {%0,%1,%2,%3};"
                 : "+f"(d[0]), "+f"(d[1]), "+f"(d[2]), "+f"(d[3])
                 : "r"(a[0]), "r"(a[1]), "r"(a[2]), "r"(a[3]), "r"(b[0]), "r"(b[1]));
}

#define NSTG 3
#define STAGE_BYTES 32768           // 16KB A + 16KB B ; one stage = K-chunk of 64 halves
#define GEMM_SMEM_BYTES (NSTG * STAGE_BYTES)   // 96KB -> 2 CTAs/SM

// ============== fp16 mma.sync NT GEMM: D = A[M,K] * B[N,K]^T, fp32 accum ==
// CTA tile 128x128; 4 warps (2 over M x 2 over N), warp tile 64x64.
// cp.async issues for chunk kt+2 are spread across the 4 ks-steps of chunk kt.
// EPI: 0 = half: acc+bias ; 1 = half: gelu(acc+bias) ; 2 = float: C += acc+bias ;
//      3 = half: acc*alpha ; 4 = half: acc
template<int EPI, bool CSKIP, bool CK>
__global__ void __launch_bounds__(128) hgemm(
    const __half* __restrict__ A, const __half* __restrict__ B,
    const float* __restrict__ bias, void* __restrict__ Cv,
    int K, int lda, int ldb, int ldc,
    long long sA, long long sB, long long sC, float alpha)
{
    extern __shared__ __align__(1024) char smem[];
    const int m0 = blockIdx.y * 128;
    const int n0 = blockIdx.x * 128;
    if (CSKIP && n0 > m0 + 127) return;
    A += (long long)blockIdx.z * sA;
    B += (long long)blockIdx.z * sB;

    const int tid = threadIdx.x;
    const int lane = tid & 31;
    const int wid = tid >> 5;          // 0..3
    const int warp_m = wid & 1;        // 2 warps over M (64 rows each)
    const int warp_n = wid >> 1;       // 2 warps over N (64 cols each)
    const uint32_t sbase = smem_u32(smem);

    const int kEnd = CK ? min(K, m0 + 128) : K;
    const int ktiles = kEnd >> 6;      // chunks of 64 halves

    // full-burst issue (prologue only)
    auto issue_tile = [&](int kt) {
        if (kt < ktiles) {
            const int k0 = kt << 6;
            const uint32_t stg = sbase + (uint32_t)(kt % NSTG) * STAGE_BYTES;
            #pragma unroll
            for (int r = 0; r < 8; r++) {
                int f = tid + (r << 7);
                int row = f >> 3, c = f & 7;           // c = 16B chunk (8 halves)
                uint32_t soff = ((uint32_t)row << 7) + ((uint32_t)(c ^ (row & 7)) << 4);
                cp_async16(stg + soff,
                           A + (long long)(m0 + row) * lda + k0 + (c << 3));
                cp_async16(stg + 16384 + soff,
                           B + (long long)(n0 + row) * ldb + k0 + (c << 3));
            }
        }
        CP_COMMIT();
    };

    float acc[4][8][4];
    #pragma unroll
    for (int i = 0; i < 4; i++)
        #pragma unroll
        for (int j = 0; j < 8; j++)
            #pragma unroll
            for (int q = 0; q < 4; q++) acc[i][j][q] = 0.f;

    const int x7 = lane & 7;
    const int aRowL = ((lane >> 3) & 1) * 8 + x7;
    const int aChunk0 = (lane >> 4);
    const int bRowL = (lane >> 4) * 8 + x7;
    const int bChunk0 = (lane >> 3) & 1;

    issue_tile(0);
    issue_tile(1);

    for (int kt = 0; kt < ktiles; kt++) {
        CP_WAIT(1);            // chunk kt resident
        __syncthreads();       // buffer (kt+2)%NSTG free for refill

        const uint32_t stgA = sbase + (uint32_t)(kt % NSTG) * STAGE_BYTES;
        const uint32_t stgB = stgA + 16384;

        const int kt2 = kt + 2;
        const bool do_issue = (kt2 < ktiles);
        const int k0n = kt2 << 6;
        const uint32_t stgN = sbase + (uint32_t)(kt2 % NSTG) * STAGE_BYTES;

        #pragma unroll
        for (int ks = 0; ks < 4; ks++) {   // each ks = k16
            // ---- spread issue: 2 r-iters (4 cp.async) per ks ----
            if (do_issue) {
                #pragma unroll
                for (int rr = 0; rr < 2; rr++) {
                    int f = tid + ((ks * 2 + rr) << 7);
                    int row = f >> 3, c = f & 7;
                    uint32_t soff = ((uint32_t)row << 7) + ((uint32_t)(c ^ (row & 7)) << 4);
                    cp_async16(stgN + soff,
                               A + (long long)(m0 + row) * lda + k0n + (c << 3));
                    cp_async16(stgN + 16384 + soff,
                               B + (long long)(n0 + row) * ldb + k0n + (c << 3));
                }
            }
            uint32_t af[4][4];
            #pragma unroll
            for (int mi = 0; mi < 4; mi++) {
                int row = warp_m * 64 + mi * 16 + aRowL;
                uint32_t addr = stgA + ((uint32_t)row << 7)
                              + ((uint32_t)((ks * 2 + aChunk0) ^ x7) << 4);
                ldsm4(af[mi][0], af[mi][1], af[mi][2], af[mi][3], addr);
            }
            uint32_t bf[8][2];
            #pragma unroll
            for (int nb = 0; nb < 4; nb++) {
                int row = warp_n * 64 + nb * 16 + bRowL;
                uint32_t addr = stgB + ((uint32_t)row << 7)
                              + ((uint32_t)((ks * 2 + bChunk0) ^ x7) << 4);
                uint32_t r0, r1, r2, r3;
                ldsm4(r0, r1, r2, r3, addr);
                bf[nb * 2][0] = r0;     bf[nb * 2][1] = r1;
                bf[nb * 2 + 1][0] = r2; bf[nb * 2 + 1][1] = r3;
            }
            #pragma unroll
            for (int mi = 0; mi < 4; mi++)
                #pragma unroll
                for (int ni = 0; ni < 8; ni++)
                    mma_f16(acc[mi][ni], af[mi], bf[ni]);
        }
        CP_COMMIT();           // close chunk kt+2's group
    }

    // ---- epilogue ----
    const int erow = lane >> 2;
    const int ecol = 2 * (lane & 3);
    #pragma unroll
    for (int mi = 0; mi < 4; mi++) {
        #pragma unroll
        for (int ni = 0; ni < 8; ni++) {
            int mbase = m0 + warp_m * 64 + mi * 16 + erow;
            int nn = n0 + warp_n * 64 + ni * 8 + ecol;
            #pragma unroll
            for (int h = 0; h < 2; h++) {
                int m = mbase + h * 8;
                float v0 = acc[mi][ni][h * 2 + 0];
                float v1 = acc[mi][ni][h * 2 + 1];
                if (EPI == 0 || EPI == 1) {
                    float2 bb = *(const float2*)(bias + nn);
                    v0 += bb.x; v1 += bb.y;
                    if (EPI == 1) {
                        v0 = 0.5f * v0 * (1.0f + erff(v0 * 0.70710678118654752f));
                        v1 = 0.5f * v1 * (1.0f + erff(v1 * 0.70710678118654752f));
                    }
                    __half* Ch = (__half*)Cv + blockIdx.z * sC;
                    *(__half2*)(Ch + (long long)m * ldc + nn) = __floats2half2_rn(v0, v1);
                } else if (EPI == 4) {
                    __half* Ch = (__half*)Cv + blockIdx.z * sC;
                    *(__half2*)(Ch + (long long)m * ldc + nn) = __floats2half2_rn(v0, v1);
                } else if (EPI == 3) {   // half: acc*alpha (scores)
                    __half* Ch = (__half*)Cv + blockIdx.z * sC;
                    *(__half2*)(Ch + (long long)m * ldc + nn) =
                        __floats2half2_rn(v0 * alpha, v1 * alpha);
                } else {   // EPI == 2: float accumulate + bias
                    float* Cf = (float*)Cv + blockIdx.z * sC;
                    float2 bb = *(const float2*)(bias + nn);
                    float* cp = Cf + (long long)m * ldc + nn;
                    float2 cv = *(const float2*)cp;
                    float2 o; o.x = cv.x + v0 + bb.x; o.y = cv.y + v1 + bb.y;
                    *(float2*)cp = o;
                }
            }
        }
    }
}

// ---------------- elementwise / reductions ----------------
__device__ __forceinline__ float warpSum(float v) {
    #pragma unroll
    for (int o = 16; o > 0; o >>= 1) v += __shfl_xor_sync(0xffffffffu, v, o);
    return v;
}
__device__ __forceinline__ float warpMax(float v) {
    #pragma unroll
    for (int o = 16; o > 0; o >>= 1) v = fmaxf(v, __shfl_xor_sync(0xffffffffu, v, o));
    return v;
}
__device__ __forceinline__ float blockSum(float v) {
    __shared__ float sh[8];
    int w = threadIdx.x >> 5, l = threadIdx.x & 31;
    v = warpSum(v);
    __syncthreads();
    if (l == 0) sh[w] = v;
    __syncthreads();
    float t = 0.f;
    #pragma unroll
    for (int i = 0; i < 8; i++) t += sh[i];
    return t;
}
__device__ __forceinline__ float blockMax(float v) {
    __shared__ float sh[8];
    int w = threadIdx.x >> 5, l = threadIdx.x & 31;
    v = warpMax(v);
    __syncthreads();
    if (l == 0) sh[w] = v;
    __syncthreads();
    float t = -INFINITY;
    #pragma unroll
    for (int i = 0; i < 8; i++) t = fmaxf(t, sh[i]);
    return t;
}

__global__ void copy4_kernel(const float4* __restrict__ src, float4* __restrict__ dst, int n4) {
    int i = blockIdx.x * 256 + threadIdx.x;
    if (i < n4) dst[i] = src[i];
}

// convert ALL weight arrays fp32 -> fp16 in one launch
#define N4_QKV (8*3*C_*C_/4)
#define N4_OUT (8*C_*C_/4)
#define N4_FF0 (8*F_*C_/4)
#define N4_FF3 (8*C_*F_/4)
__global__ void convert_all_kernel(const float4* __restrict__ qkv_w, __half* __restrict__ wqkv,
                                   const float4* __restrict__ out_w, __half* __restrict__ wout,
                                   const float4* __restrict__ ff0_w, __half* __restrict__ wff0,
                                   const float4* __restrict__ ff3_w, __half* __restrict__ wff3)
{
    long long i = (long long)blockIdx.x * 256 + threadIdx.x;
    const float4* src; __half* dst; long long off;
    if (i < N4_QKV)                         { src = qkv_w; dst = wqkv; off = i; }
    else if (i < N4_QKV + N4_OUT)           { src = out_w; dst = wout; off = i - N4_QKV; }
    else if (i < N4_QKV + N4_OUT + N4_FF0)  { src = ff0_w; dst = wff0; off = i - N4_QKV - N4_OUT; }
    else if (i < N4_QKV + N4_OUT + N4_FF0 + N4_FF3)
                                            { src = ff3_w; dst = wff3; off = i - N4_QKV - N4_OUT - N4_FF0; }
    else return;
    float4 v = src[off];
    __half2* d2 = (__half2*)(dst + off * 4);
    d2[0] = __floats2half2_rn(v.x, v.y);
    d2[1] = __floats2half2_rn(v.z, v.w);
}

__global__ void __launch_bounds__(256) ln_kernel(
    const float* __restrict__ x, const float* __restrict__ w,
    const float* __restrict__ b, __half* __restrict__ out)
{
    size_t row = blockIdx.x;
    const float4* xr = (const float4*)(x + row * C_);
    int tid = threadIdx.x;
    float4 v = xr[tid];
    float s = blockSum(v.x + v.y + v.z + v.w);
    float mean = s * (1.0f / C_);
    float d0 = v.x - mean, d1 = v.y - mean, d2 = v.z - mean, d3 = v.w - mean;
    float q = blockSum(d0*d0 + d1*d1 + d2*d2 + d3*d3);
    float inv = rsqrtf(q * (1.0f / C_) + 1e-5f);
    float4 wv = ((const float4*)w)[tid];
    float4 bv = ((const float4*)b)[tid];
    __half2* o2 = (__half2*)(out + row * C_);
    o2[tid * 2 + 0] = __floats2half2_rn(d0 * inv * wv.x + bv.x, d1 * inv * wv.y + bv.y);
    o2[tid * 2 + 1] = __floats2half2_rn(d2 * inv * wv.z + bv.z, d3 * inv * wv.w + bv.w);
}

// causal softmax, IN PLACE on fp16 buffer (zero-filled to 128-boundary)
__global__ void __launch_bounds__(256) softmax_kernel(__half* __restrict__ att)
{
    int r = blockIdx.x;
    int b = r >> 11;
    int t = r & (T_ - 1);
    __half* row = att + ((size_t)b * T_ + t) * T_;
    int n = t + 1;                        // valid entries
    int nw = (n + 127) & ~127;            // zero-fill through causal 128-boundary
    int tid = threadIdx.x;
    float vals[8];
    float vmax = -INFINITY;
    #pragma unroll
    for (int it = 0; it < 8; it++) {
        int i = tid + it * 256;
        vals[it] = (i < n) ? __half2float(row[i]) : -INFINITY;
        vmax = fmaxf(vmax, vals[it]);
    }
    vmax = blockMax(vmax);
    float s = 0.f;
    #pragma unroll
    for (int it = 0; it < 8; it++) {
        int i = tid + it * 256;
        if (i < n) { vals[it] = expf(vals[it] - vmax); s += vals[it]; }
        else vals[it] = 0.f;
    }
    s = blockSum(s);
    float inv = 1.0f / s;
    #pragma unroll
    for (int it = 0; it < 8; it++) {
        int i = tid + it * 256;
        if (i < nw) row[i] = __float2half_rn(vals[it] * inv);
    }
}

// v[b][t][c] (inside qkv halves, offset 2C, row stride 3C) -> vt[b][c][t]
__global__ void transpose_v_kernel(const __half* __restrict__ qkv, __half* __restrict__ vt)
{
    __shared__ __half tile[32][33];
    int b = blockIdx.z;
    int t0 = blockIdx.x * 32, c0 = blockIdx.y * 32;
    int tx = threadIdx.x, ty = threadIdx.y;   // 32 x 8
    #pragma unroll
    for (int r = 0; r < 32; r += 8)
        tile[ty + r][tx] = qkv[((long long)b * T_ + t0 + ty + r) * 3 * C_ + 2 * C_ + c0 + tx];
    __syncthreads();
    #pragma unroll
    for (int r = 0; r < 32; r += 8)
        vt[((long long)b * C_ + c0 + ty + r) * T_ + t0 + tx] = tile[tx][ty + r];
}

// ---------------- host launcher ----------------
extern "C" void kernel_launch(void* const* d_in, const int* in_sizes, int n_in,
                              void* d_out, int out_size)
{
    const float* x     = (const float*)d_in[0];
    const float* ln1_w = (const float*)d_in[1];
    const float* ln1_b = (const float*)d_in[2];
    const float* qkv_w = (const float*)d_in[3];
    const float* qkv_b = (const float*)d_in[4];
    const float* out_w = (const float*)d_in[5];
    const float* out_b = (const float*)d_in[6];
    const float* ln2_w = (const float*)d_in[7];
    const float* ln2_b = (const float*)d_in[8];
    const float* ff0_w = (const float*)d_in[9];
    const float* ff0_b = (const float*)d_in[10];
    const float* ff3_w = (const float*)d_in[11];
    const float* ff3_b = (const float*)d_in[12];

    float *gx;
    __half *gh, *gqkv, *gatt, *gao, *gvt, *gff;
    __half *wqkv, *wout, *wff0, *wff3;
    cudaGetSymbolAddress((void**)&gx,   g_x);
    cudaGetSymbolAddress((void**)&gh,   g_h);
    cudaGetSymbolAddress((void**)&gqkv, g_qkv);
    cudaGetSymbolAddress((void**)&gatt, g_att);
    cudaGetSymbolAddress((void**)&gao,  g_ao);
    cudaGetSymbolAddress((void**)&gvt,  g_vt);
    cudaGetSymbolAddress((void**)&gff,  g_ff);
    cudaGetSymbolAddress((void**)&wqkv, g_wqkv);
    cudaGetSymbolAddress((void**)&wout, g_wout);
    cudaGetSymbolAddress((void**)&wff0, g_wff0);
    cudaGetSymbolAddress((void**)&wff3, g_wff3);

    cudaFuncSetAttribute(hgemm<0,false,false>, cudaFuncAttributeMaxDynamicSharedMemorySize, GEMM_SMEM_BYTES);
    cudaFuncSetAttribute(hgemm<1,false,false>, cudaFuncAttributeMaxDynamicSharedMemorySize, GEMM_SMEM_BYTES);
    cudaFuncSetAttribute(hgemm<2,false,false>, cudaFuncAttributeMaxDynamicSharedMemorySize, GEMM_SMEM_BYTES);
    cudaFuncSetAttribute(hgemm<3,true,false>,  cudaFuncAttributeMaxDynamicSharedMemorySize, GEMM_SMEM_BYTES);
    cudaFuncSetAttribute(hgemm<4,false,true>,  cudaFuncAttributeMaxDynamicSharedMemorySize, GEMM_SMEM_BYTES);

    // (1) convert all weights to fp16 in ONE launch
    {
        long long total4 = (long long)N4_QKV + N4_OUT + N4_FF0 + N4_FF3;
        int blocks = (int)((total4 + 255) / 256);
        convert_all_kernel<<<blocks, 256>>>(
            (const float4*)qkv_w, wqkv,
            (const float4*)out_w, wout,
            (const float4*)ff0_w, wff0,
            (const float4*)ff3_w, wff3);
    }

    const int n4 = MROWS * C_ / 4;
    // (2) residual init
    copy4_kernel<<<(n4 + 255) / 256, 256>>>((const float4*)x, (float4*)gx, n4);

    const float scale = 0.03125f;   // 1/sqrt(1024)

    for (int i = 0; i < 8; i++) {
        // (3) LN1 -> fp16
        ln_kernel<<<MROWS, 256>>>(gx, ln1_w + (size_t)i * C_, ln1_b + (size_t)i * C_, gh);
        // (4) qkv = h @ qkv_w^T + qkv_b  -> fp16
        hgemm<0,false,false><<<dim3(3*C_/128, MROWS/128), 128, GEMM_SMEM_BYTES>>>(
            gh, wqkv + (size_t)i * 3 * C_ * C_, qkv_b + (size_t)i * 3 * C_, gqkv,
            C_, C_, C_, 3*C_, 0, 0, 0, 1.0f);
        // (5) v^T per batch (fp16)
        transpose_v_kernel<<<dim3(T_/32, C_/32, B_), dim3(32, 8)>>>(gqkv, gvt);
        // (6) scores = (q @ k^T) * scale  -> fp16 (in att buffer)
        hgemm<3,true,false><<<dim3(T_/128, T_/128, B_), 128, GEMM_SMEM_BYTES>>>(
            gqkv, gqkv + C_, (const float*)0, gatt,
            C_, 3*C_, 3*C_, T_,
            (long long)T_ * 3 * C_, (long long)T_ * 3 * C_, (long long)T_ * T_, scale);
        // (7) causal softmax in place (zeros through 128-boundary)
        softmax_kernel<<<MROWS, 256>>>(gatt);
        // (8) ao = probs @ v  (NT with B=vt, K clipped) -> fp16
        hgemm<4,false,true><<<dim3(C_/128, T_/128, B_), 128, GEMM_SMEM_BYTES>>>(
            gatt, gvt, (const float*)0, gao,
            T_, T_, T_, C_,
            (long long)T_ * T_, (long long)C_ * T_, (long long)T_ * C_, 1.0f);
        // (9) x += ao @ out_w^T + out_b  (fp32 residual)
        hgemm<2,false,false><<<dim3(C_/128, MROWS/128), 128, GEMM_SMEM_BYTES>>>(
            gao, wout + (size_t)i * C_ * C_, out_b + (size_t)i * C_, gx,
            C_, C_, C_, C_, 0, 0, 0, 1.0f);
        // (10) LN2 -> fp16
        ln_kernel<<<MROWS, 256>>>(gx, ln2_w + (size_t)i * C_, ln2_b + (size_t)i * C_, gh);
        // (11) ff = gelu(h2 @ ff0_w^T + ff0_b) -> fp16
        hgemm<1,false,false><<<dim3(F_/128, MROWS/128), 128, GEMM_SMEM_BYTES>>>(
            gh, wff0 + (size_t)i * F_ * C_, ff0_b + (size_t)i * F_, gff,
            C_, C_, C_, F_, 0, 0, 0, 1.0f);
        // (12) x += ff @ ff3_w^T + ff3_b  (fp32 residual)
        hgemm<2,false,false><<<dim3(C_/128, MROWS/128), 128, GEMM_SMEM_BYTES>>>(
            gff, wff3 + (size_t)i * C_ * F_, ff3_b + (size_t)i * C_, gx,
            F_, F_, F_, C_, 0, 0, 0, 1.0f);
    }

    copy4_kernel<<<(n4 + 255) / 256, 256>>>((const float4*)gx, (float4*)d_out, n4);
}

// round 13
// speedup vs baseline: 1.0395x; 1.0395x over previous
#include <cuda_runtime.h>
#include <cuda_fp16.h>
#include <math.h>
#include <stdint.h>

#define B_ 4
#define T_ 2048
#define C_ 1024
#define F_ 4096
#define MROWS (B_*T_)   // 8192

// ---------------- scratch (device globals; no allocation allowed) ----------
__device__ __align__(128) float  g_x[(size_t)MROWS*C_];        // residual (fp32)
__device__ __align__(128) __half g_h[(size_t)MROWS*C_];        // LN out
__device__ __align__(128) __half g_qkv[(size_t)MROWS*3*C_];
__device__ __align__(128) __half g_att[(size_t)B_*T_*T_];      // scores -> probs (in place)
__device__ __align__(128) __half g_ao[(size_t)MROWS*C_];
__device__ __align__(128) __half g_vt[(size_t)B_*C_*T_];       // v^T per batch
__device__ __align__(128) __half g_ff[(size_t)MROWS*F_];
// fp16 weights
__device__ __align__(128) __half g_wqkv[(size_t)8*3*C_*C_];
__device__ __align__(128) __half g_wout[(size_t)8*C_*C_];
__device__ __align__(128) __half g_wff0[(size_t)8*F_*C_];
__device__ __align__(128) __half g_wff3[(size_t)8*C_*F_];

// ================= base-target PTX helpers =================
__device__ __forceinline__ uint32_t smem_u32(const void* p) {
    uint32_t a;
    asm("{ .reg .u64 t; cvta.to.shared.u64 t, %1; cvt.u32.u64 %0, t; }" : "=r"(a) : "l"(p));
    return a;
}
__device__ __forceinline__ void cp_async16(uint32_t saddr, const void* gptr) {
    asm volatile("cp.async.cg.shared.global [%0], [%1], 16;" :: "r"(saddr), "l"(gptr) : "memory");
}
#define CP_COMMIT()  asm volatile("cp.async.commit_group;" ::: "memory")
#define CP_WAIT(n)   asm volatile("cp.async.wait_group %0;" :: "n"(n) : "memory")

__device__ __forceinline__ void ldsm4(uint32_t& r0, uint32_t& r1, uint32_t& r2, uint32_t& r3,
                                      uint32_t addr) {
    asm volatile("ldmatrix.sync.aligned.m8n8.x4.shared.b16 {%0,%1,%2,%3}, [%4];"
                 : "=r"(r0), "=r"(r1), "=r"(r2), "=r"(r3) : "r"(addr));
}
__device__ __forceinline__ void mma_f16(float* d, const uint32_t* a, const uint32_t* b) {
    asm volatile("mma.sync.aligned.m16n8k16.row.col.f32.f16.f16.f32 "
                 "{%0,%1,%2,%3}, {%4,%5,%6,%7}, {%8,%9}, {%0,%1,%2,%3};"
                 : "+f"(d[0]), "+f"(d[1]), "+f"(d[2]), "+f"(d[3])
                 : "r"(a[0]), "r"(a[1]), "r"(a[2]), "r"(a[3]), "r"(b[0]), "r"(b[1]));
}

#define NSTG 3
#define STAGE_BYTES 32768           // 16KB A + 16KB B ; one stage = K-chunk of 64 halves
#define GEMM_SMEM_BYTES (NSTG * STAGE_BYTES)   // 96KB -> 2 CTAs/SM

// ============== fp16 mma.sync NT GEMM: D = A[M,K] * B[N,K]^T, fp32 accum ==
// CTA tile 128x128; 4 warps (2 over M x 2 over N), warp tile 64x64.
// R10-proven body: burst cp.async issue after barrier, plain ks load+mma loop.
// EPI: 0 = half: acc+bias ; 1 = half: gelu(acc+bias) ; 2 = float: C += acc+bias ;
//      3 = half: acc*alpha ; 4 = half: acc
template<int EPI, bool CSKIP, bool CK>
__global__ void __launch_bounds__(128) hgemm(
    const __half* __restrict__ A, const __half* __restrict__ B,
    const float* __restrict__ bias, void* __restrict__ Cv,
    int K, int lda, int ldb, int ldc,
    long long sA, long long sB, long long sC, float alpha)
{
    extern __shared__ __align__(1024) char smem[];
    const int m0 = blockIdx.y * 128;
    const int n0 = blockIdx.x * 128;
    if (CSKIP && n0 > m0 + 127) return;
    A += (long long)blockIdx.z * sA;
    B += (long long)blockIdx.z * sB;

    const int tid = threadIdx.x;
    const int lane = tid & 31;
    const int wid = tid >> 5;          // 0..3
    const int warp_m = wid & 1;        // 2 warps over M (64 rows each)
    const int warp_n = wid >> 1;       // 2 warps over N (64 cols each)
    const uint32_t sbase = smem_u32(smem);

    const int kEnd = CK ? min(K, m0 + 128) : K;
    const int ktiles = kEnd >> 6;      // chunks of 64 halves

    auto issue_tile = [&](int kt) {
        if (kt < ktiles) {
            const int k0 = kt << 6;
            const uint32_t stg = sbase + (uint32_t)(kt % NSTG) * STAGE_BYTES;
            #pragma unroll
            for (int r = 0; r < 8; r++) {
                int f = tid + (r << 7);
                int row = f >> 3, c = f & 7;           // c = 16B chunk (8 halves)
                uint32_t soff = ((uint32_t)row << 7) + ((uint32_t)(c ^ (row & 7)) << 4);
                cp_async16(stg + soff,
                           A + (long long)(m0 + row) * lda + k0 + (c << 3));
                cp_async16(stg + 16384 + soff,
                           B + (long long)(n0 + row) * ldb + k0 + (c << 3));
            }
        }
        CP_COMMIT();
    };

    float acc[4][8][4];
    #pragma unroll
    for (int i = 0; i < 4; i++)
        #pragma unroll
        for (int j = 0; j < 8; j++)
            #pragma unroll
            for (int q = 0; q < 4; q++) acc[i][j][q] = 0.f;

    const int x7 = lane & 7;
    const int aRowL = ((lane >> 3) & 1) * 8 + x7;
    const int aChunk0 = (lane >> 4);
    const int bRowL = (lane >> 4) * 8 + x7;
    const int bChunk0 = (lane >> 3) & 1;

    issue_tile(0);
    issue_tile(1);

    for (int kt = 0; kt < ktiles; kt++) {
        CP_WAIT(1);
        __syncthreads();
        issue_tile(kt + 2);

        const uint32_t stgA = sbase + (uint32_t)(kt % NSTG) * STAGE_BYTES;
        const uint32_t stgB = stgA + 16384;

        #pragma unroll
        for (int ks = 0; ks < 4; ks++) {   // each ks = k16
            uint32_t af[4][4];
            #pragma unroll
            for (int mi = 0; mi < 4; mi++) {
                int row = warp_m * 64 + mi * 16 + aRowL;
                uint32_t addr = stgA + ((uint32_t)row << 7)
                              + ((uint32_t)((ks * 2 + aChunk0) ^ x7) << 4);
                ldsm4(af[mi][0], af[mi][1], af[mi][2], af[mi][3], addr);
            }
            uint32_t bf[8][2];
            #pragma unroll
            for (int nb = 0; nb < 4; nb++) {
                int row = warp_n * 64 + nb * 16 + bRowL;
                uint32_t addr = stgB + ((uint32_t)row << 7)
                              + ((uint32_t)((ks * 2 + bChunk0) ^ x7) << 4);
                uint32_t r0, r1, r2, r3;
                ldsm4(r0, r1, r2, r3, addr);
                bf[nb * 2][0] = r0;     bf[nb * 2][1] = r1;
                bf[nb * 2 + 1][0] = r2; bf[nb * 2 + 1][1] = r3;
            }
            #pragma unroll
            for (int mi = 0; mi < 4; mi++)
                #pragma unroll
                for (int ni = 0; ni < 8; ni++)
                    mma_f16(acc[mi][ni], af[mi], bf[ni]);
        }
    }

    // ---- epilogue ----
    const int erow = lane >> 2;
    const int ecol = 2 * (lane & 3);
    #pragma unroll
    for (int mi = 0; mi < 4; mi++) {
        #pragma unroll
        for (int ni = 0; ni < 8; ni++) {
            int mbase = m0 + warp_m * 64 + mi * 16 + erow;
            int nn = n0 + warp_n * 64 + ni * 8 + ecol;
            #pragma unroll
            for (int h = 0; h < 2; h++) {
                int m = mbase + h * 8;
                float v0 = acc[mi][ni][h * 2 + 0];
                float v1 = acc[mi][ni][h * 2 + 1];
                if (EPI == 0 || EPI == 1) {
                    float2 bb = *(const float2*)(bias + nn);
                    v0 += bb.x; v1 += bb.y;
                    if (EPI == 1) {
                        v0 = 0.5f * v0 * (1.0f + erff(v0 * 0.70710678118654752f));
                        v1 = 0.5f * v1 * (1.0f + erff(v1 * 0.70710678118654752f));
                    }
                    __half* Ch = (__half*)Cv + blockIdx.z * sC;
                    *(__half2*)(Ch + (long long)m * ldc + nn) = __floats2half2_rn(v0, v1);
                } else if (EPI == 4) {
                    __half* Ch = (__half*)Cv + blockIdx.z * sC;
                    *(__half2*)(Ch + (long long)m * ldc + nn) = __floats2half2_rn(v0, v1);
                } else if (EPI == 3) {   // half: acc*alpha (scores)
                    __half* Ch = (__half*)Cv + blockIdx.z * sC;
                    *(__half2*)(Ch + (long long)m * ldc + nn) =
                        __floats2half2_rn(v0 * alpha, v1 * alpha);
                } else {   // EPI == 2: float accumulate + bias
                    float* Cf = (float*)Cv + blockIdx.z * sC;
                    float2 bb = *(const float2*)(bias + nn);
                    float* cp = Cf + (long long)m * ldc + nn;
                    float2 cv = *(const float2*)cp;
                    float2 o; o.x = cv.x + v0 + bb.x; o.y = cv.y + v1 + bb.y;
                    *(float2*)cp = o;
                }
            }
        }
    }
}

// ---------------- elementwise / reductions ----------------
__device__ __forceinline__ float warpSum(float v) {
    #pragma unroll
    for (int o = 16; o > 0; o >>= 1) v += __shfl_xor_sync(0xffffffffu, v, o);
    return v;
}
__device__ __forceinline__ float warpMax(float v) {
    #pragma unroll
    for (int o = 16; o > 0; o >>= 1) v = fmaxf(v, __shfl_xor_sync(0xffffffffu, v, o));
    return v;
}
__device__ __forceinline__ float blockSum(float v) {
    __shared__ float sh[8];
    int w = threadIdx.x >> 5, l = threadIdx.x & 31;
    v = warpSum(v);
    __syncthreads();
    if (l == 0) sh[w] = v;
    __syncthreads();
    float t = 0.f;
    #pragma unroll
    for (int i = 0; i < 8; i++) t += sh[i];
    return t;
}
__device__ __forceinline__ float blockMax(float v) {
    __shared__ float sh[8];
    int w = threadIdx.x >> 5, l = threadIdx.x & 31;
    v = warpMax(v);
    __syncthreads();
    if (l == 0) sh[w] = v;
    __syncthreads();
    float t = -INFINITY;
    #pragma unroll
    for (int i = 0; i < 8; i++) t = fmaxf(t, sh[i]);
    return t;
}

__global__ void copy4_kernel(const float4* __restrict__ src, float4* __restrict__ dst, int n4) {
    int i = blockIdx.x * 256 + threadIdx.x;
    if (i < n4) dst[i] = src[i];
}

// convert ALL weight arrays fp32 -> fp16 in one launch
#define N4_QKV (8*3*C_*C_/4)
#define N4_OUT (8*C_*C_/4)
#define N4_FF0 (8*F_*C_/4)
#define N4_FF3 (8*C_*F_/4)
__global__ void convert_all_kernel(const float4* __restrict__ qkv_w, __half* __restrict__ wqkv,
                                   const float4* __restrict__ out_w, __half* __restrict__ wout,
                                   const float4* __restrict__ ff0_w, __half* __restrict__ wff0,
                                   const float4* __restrict__ ff3_w, __half* __restrict__ wff3)
{
    long long i = (long long)blockIdx.x * 256 + threadIdx.x;
    const float4* src; __half* dst; long long off;
    if (i < N4_QKV)                         { src = qkv_w; dst = wqkv; off = i; }
    else if (i < N4_QKV + N4_OUT)           { src = out_w; dst = wout; off = i - N4_QKV; }
    else if (i < N4_QKV + N4_OUT + N4_FF0)  { src = ff0_w; dst = wff0; off = i - N4_QKV - N4_OUT; }
    else if (i < N4_QKV + N4_OUT + N4_FF0 + N4_FF3)
                                            { src = ff3_w; dst = wff3; off = i - N4_QKV - N4_OUT - N4_FF0; }
    else return;
    float4 v = src[off];
    __half2* d2 = (__half2*)(dst + off * 4);
    d2[0] = __floats2half2_rn(v.x, v.y);
    d2[1] = __floats2half2_rn(v.z, v.w);
}

__global__ void __launch_bounds__(256) ln_kernel(
    const float* __restrict__ x, const float* __restrict__ w,
    const float* __restrict__ b, __half* __restrict__ out)
{
    size_t row = blockIdx.x;
    const float4* xr = (const float4*)(x + row * C_);
    int tid = threadIdx.x;
    float4 v = xr[tid];
    float s = blockSum(v.x + v.y + v.z + v.w);
    float mean = s * (1.0f / C_);
    float d0 = v.x - mean, d1 = v.y - mean, d2 = v.z - mean, d3 = v.w - mean;
    float q = blockSum(d0*d0 + d1*d1 + d2*d2 + d3*d3);
    float inv = rsqrtf(q * (1.0f / C_) + 1e-5f);
    float4 wv = ((const float4*)w)[tid];
    float4 bv = ((const float4*)b)[tid];
    __half2* o2 = (__half2*)(out + row * C_);
    o2[tid * 2 + 0] = __floats2half2_rn(d0 * inv * wv.x + bv.x, d1 * inv * wv.y + bv.y);
    o2[tid * 2 + 1] = __floats2half2_rn(d2 * inv * wv.z + bv.z, d3 * inv * wv.w + bv.w);
}

// causal softmax, IN PLACE on fp16 buffer (zero-filled to 128-boundary)
__global__ void __launch_bounds__(256) softmax_kernel(__half* __restrict__ att)
{
    int r = blockIdx.x;
    int b = r >> 11;
    int t = r & (T_ - 1);
    __half* row = att + ((size_t)b * T_ + t) * T_;
    int n = t + 1;                        // valid entries
    int nw = (n + 127) & ~127;            // zero-fill through causal 128-boundary
    int tid = threadIdx.x;
    float vals[8];
    float vmax = -INFINITY;
    #pragma unroll
    for (int it = 0; it < 8; it++) {
        int i = tid + it * 256;
        vals[it] = (i < n) ? __half2float(row[i]) : -INFINITY;
        vmax = fmaxf(vmax, vals[it]);
    }
    vmax = blockMax(vmax);
    float s = 0.f;
    #pragma unroll
    for (int it = 0; it < 8; it++) {
        int i = tid + it * 256;
        if (i < n) { vals[it] = expf(vals[it] - vmax); s += vals[it]; }
        else vals[it] = 0.f;
    }
    s = blockSum(s);
    float inv = 1.0f / s;
    #pragma unroll
    for (int it = 0; it < 8; it++) {
        int i = tid + it * 256;
        if (i < nw) row[i] = __float2half_rn(vals[it] * inv);
    }
}

// v[b][t][c] (inside qkv halves, offset 2C, row stride 3C) -> vt[b][c][t]
__global__ void transpose_v_kernel(const __half* __restrict__ qkv, __half* __restrict__ vt)
{
    __shared__ __half tile[32][33];
    int b = blockIdx.z;
    int t0 = blockIdx.x * 32, c0 = blockIdx.y * 32;
    int tx = threadIdx.x, ty = threadIdx.y;   // 32 x 8
    #pragma unroll
    for (int r = 0; r < 32; r += 8)
        tile[ty + r][tx] = qkv[((long long)b * T_ + t0 + ty + r) * 3 * C_ + 2 * C_ + c0 + tx];
    __syncthreads();
    #pragma unroll
    for (int r = 0; r < 32; r += 8)
        vt[((long long)b * C_ + c0 + ty + r) * T_ + t0 + tx] = tile[tx][ty + r];
}

// ---------------- host launcher ----------------
extern "C" void kernel_launch(void* const* d_in, const int* in_sizes, int n_in,
                              void* d_out, int out_size)
{
    const float* x     = (const float*)d_in[0];
    const float* ln1_w = (const float*)d_in[1];
    const float* ln1_b = (const float*)d_in[2];
    const float* qkv_w = (const float*)d_in[3];
    const float* qkv_b = (const float*)d_in[4];
    const float* out_w = (const float*)d_in[5];
    const float* out_b = (const float*)d_in[6];
    const float* ln2_w = (const float*)d_in[7];
    const float* ln2_b = (const float*)d_in[8];
    const float* ff0_w = (const float*)d_in[9];
    const float* ff0_b = (const float*)d_in[10];
    const float* ff3_w = (const float*)d_in[11];
    const float* ff3_b = (const float*)d_in[12];

    float *gx;
    __half *gh, *gqkv, *gatt, *gao, *gvt, *gff;
    __half *wqkv, *wout, *wff0, *wff3;
    cudaGetSymbolAddress((void**)&gx,   g_x);
    cudaGetSymbolAddress((void**)&gh,   g_h);
    cudaGetSymbolAddress((void**)&gqkv, g_qkv);
    cudaGetSymbolAddress((void**)&gatt, g_att);
    cudaGetSymbolAddress((void**)&gao,  g_ao);
    cudaGetSymbolAddress((void**)&gvt,  g_vt);
    cudaGetSymbolAddress((void**)&gff,  g_ff);
    cudaGetSymbolAddress((void**)&wqkv, g_wqkv);
    cudaGetSymbolAddress((void**)&wout, g_wout);
    cudaGetSymbolAddress((void**)&wff0, g_wff0);
    cudaGetSymbolAddress((void**)&wff3, g_wff3);

    cudaFuncSetAttribute(hgemm<0,false,false>, cudaFuncAttributeMaxDynamicSharedMemorySize, GEMM_SMEM_BYTES);
    cudaFuncSetAttribute(hgemm<1,false,false>, cudaFuncAttributeMaxDynamicSharedMemorySize, GEMM_SMEM_BYTES);
    cudaFuncSetAttribute(hgemm<2,false,false>, cudaFuncAttributeMaxDynamicSharedMemorySize, GEMM_SMEM_BYTES);
    cudaFuncSetAttribute(hgemm<3,true,false>,  cudaFuncAttributeMaxDynamicSharedMemorySize, GEMM_SMEM_BYTES);
    cudaFuncSetAttribute(hgemm<4,false,true>,  cudaFuncAttributeMaxDynamicSharedMemorySize, GEMM_SMEM_BYTES);

    // (1) convert all weights to fp16 in ONE launch
    {
        long long total4 = (long long)N4_QKV + N4_OUT + N4_FF0 + N4_FF3;
        int blocks = (int)((total4 + 255) / 256);
        convert_all_kernel<<<blocks, 256>>>(
            (const float4*)qkv_w, wqkv,
            (const float4*)out_w, wout,
            (const float4*)ff0_w, wff0,
            (const float4*)ff3_w, wff3);
    }

    const int n4 = MROWS * C_ / 4;
    // (2) residual init
    copy4_kernel<<<(n4 + 255) / 256, 256>>>((const float4*)x, (float4*)gx, n4);

    const float scale = 0.03125f;   // 1/sqrt(1024)

    for (int i = 0; i < 8; i++) {
        // (3) LN1 -> fp16
        ln_kernel<<<MROWS, 256>>>(gx, ln1_w + (size_t)i * C_, ln1_b + (size_t)i * C_, gh);
        // (4) qkv = h @ qkv_w^T + qkv_b  -> fp16
        hgemm<0,false,false><<<dim3(3*C_/128, MROWS/128), 128, GEMM_SMEM_BYTES>>>(
            gh, wqkv + (size_t)i * 3 * C_ * C_, qkv_b + (size_t)i * 3 * C_, gqkv,
            C_, C_, C_, 3*C_, 0, 0, 0, 1.0f);
        // (5) v^T per batch (fp16)
        transpose_v_kernel<<<dim3(T_/32, C_/32, B_), dim3(32, 8)>>>(gqkv, gvt);
        // (6) scores = (q @ k^T) * scale  -> fp16 (att buffer)
        hgemm<3,true,false><<<dim3(T_/128, T_/128, B_), 128, GEMM_SMEM_BYTES>>>(
            gqkv, gqkv + C_, (const float*)0, gatt,
            C_, 3*C_, 3*C_, T_,
            (long long)T_ * 3 * C_, (long long)T_ * 3 * C_, (long long)T_ * T_, scale);
        // (7) causal softmax in place (zeros through 128-boundary)
        softmax_kernel<<<MROWS, 256>>>(gatt);
        // (8) ao = probs @ v  (NT with B=vt, K clipped) -> fp16
        hgemm<4,false,true><<<dim3(C_/128, T_/128, B_), 128, GEMM_SMEM_BYTES>>>(
            gatt, gvt, (const float*)0, gao,
            T_, T_, T_, C_,
            (long long)T_ * T_, (long long)C_ * T_, (long long)T_ * C_, 1.0f);
        // (9) x += ao @ out_w^T + out_b  (fp32 residual)
        hgemm<2,false,false><<<dim3(C_/128, MROWS/128), 128, GEMM_SMEM_BYTES>>>(
            gao, wout + (size_t)i * C_ * C_, out_b + (size_t)i * C_, gx,
            C_, C_, C_, C_, 0, 0, 0, 1.0f);
        // (10) LN2 -> fp16
        ln_kernel<<<MROWS, 256>>>(gx, ln2_w + (size_t)i * C_, ln2_b + (size_t)i * C_, gh);
        // (11) ff = gelu(h2 @ ff0_w^T + ff0_b) -> fp16
        hgemm<1,false,false><<<dim3(F_/128, MROWS/128), 128, GEMM_SMEM_BYTES>>>(
            gh, wff0 + (size_t)i * F_ * C_, ff0_b + (size_t)i * F_, gff,
            C_, C_, C_, F_, 0, 0, 0, 1.0f);
        // (12) x += ff @ ff3_w^T + ff3_b  (fp32 residual)
        hgemm<2,false,false><<<dim3(C_/128, MROWS/128), 128, GEMM_SMEM_BYTES>>>(
            gff, wff3 + (size_t)i * C_ * F_, ff3_b + (size_t)i * C_, gx,
            F_, F_, F_, C_, 0, 0, 0, 1.0f);
    }

    copy4_kernel<<<(n4 + 255) / 256, 256>>>((const float4*)gx, (float4*)d_out, n4);
}

// round 14
// speedup vs baseline: 1.1352x; 1.0920x over previous
#include <cuda_runtime.h>
#include <cuda_fp16.h>
#include <math.h>
#include <stdint.h>

#define B_ 4
#define T_ 2048
#define C_ 1024
#define F_ 4096
#define MROWS (B_*T_)   // 8192

// ---------------- scratch (device globals; no allocation allowed) ----------
__device__ __align__(128) float  g_x[(size_t)MROWS*C_];        // residual (fp32)
__device__ __align__(128) __half g_h[(size_t)MROWS*C_];        // LN out
__device__ __align__(128) __half g_qkv[(size_t)MROWS*3*C_];
__device__ __align__(128) __half g_att[(size_t)B_*T_*T_];      // scores -> probs (in place)
__device__ __align__(128) __half g_ao[(size_t)MROWS*C_];
__device__ __align__(128) __half g_vt[(size_t)B_*C_*T_];       // v^T per batch
__device__ __align__(128) __half g_ff[(size_t)MROWS*F_];
// fp16 weights
__device__ __align__(128) __half g_wqkv[(size_t)8*3*C_*C_];
__device__ __align__(128) __half g_wout[(size_t)8*C_*C_];
__device__ __align__(128) __half g_wff0[(size_t)8*F_*C_];
__device__ __align__(128) __half g_wff3[(size_t)8*C_*F_];

// ================= base-target PTX helpers =================
__device__ __forceinline__ uint32_t smem_u32(const void* p) {
    uint32_t a;
    asm("{ .reg .u64 t; cvta.to.shared.u64 t, %1; cvt.u32.u64 %0, t; }" : "=r"(a) : "l"(p));
    return a;
}
__device__ __forceinline__ void cp_async16(uint32_t saddr, const void* gptr) {
    asm volatile("cp.async.cg.shared.global [%0], [%1], 16;" :: "r"(saddr), "l"(gptr) : "memory");
}
#define CP_COMMIT()  asm volatile("cp.async.commit_group;" ::: "memory")
#define CP_WAIT(n)   asm volatile("cp.async.wait_group %0;" :: "n"(n) : "memory")

__device__ __forceinline__ void ldsm4(uint32_t& r0, uint32_t& r1, uint32_t& r2, uint32_t& r3,
                                      uint32_t addr) {
    asm volatile("ldmatrix.sync.aligned.m8n8.x4.shared.b16 {%0,%1,%2,%3}, [%4];"
                 : "=r"(r0), "=r"(r1), "=r"(r2), "=r"(r3) : "r"(addr));
}
__device__ __forceinline__ void mma_f16(float* d, const uint32_t* a, const uint32_t* b) {
    asm volatile("mma.sync.aligned.m16n8k16.row.col.f32.f16.f16.f32 "
                 "{%0,%1,%2,%3}, {%4,%5,%6,%7}, {%8,%9}, {%0,%1,%2,%3};"
                 : "+f"(d[0]), "+f"(d[1]), "+f"(d[2]), "+f"(d[3])
                 : "r"(a[0]), "r"(a[1]), "r"(a[2]), "r"(a[3]), "r"(b[0]), "r"(b[1]));
}

// FMA-pipe exp: exp(x) = 2^(x*log2e), n=rint, 5-term Taylor on 2^f, |f|<=0.5.
// rel err ~2e-6; avoids the MUFU.EX2 throughput wall (rt=8/SMSP).
__device__ __forceinline__ float fexp(float x) {
    x = fmaxf(x, -80.0f);
    float y = x * 1.4426950408889634f;
    float n = rintf(y);
    float f = y - n;
    float p = 1.33336e-3f;
    p = fmaf(p, f, 9.61813e-3f);
    p = fmaf(p, f, 5.5504108e-2f);
    p = fmaf(p, f, 2.4022651e-1f);
    p = fmaf(p, f, 6.9314718e-1f);
    p = fmaf(p, f, 1.0f);
    int e = (((int)n) + 127) << 23;
    return p * __int_as_float(e);
}

#define NSTG 3
#define STAGE_BYTES 32768           // 16KB A + 16KB B ; one stage = K-chunk of 64 halves
#define GEMM_SMEM_BYTES (NSTG * STAGE_BYTES)   // 96KB -> 2 CTAs/SM

// ============== fp16 mma.sync NT GEMM: D = A[M,K] * B[N,K]^T, fp32 accum ==
// CTA tile 128x128; 4 warps (2 over M x 2 over N), warp tile 64x64.
// R10/R13-proven body: burst cp.async issue after barrier, plain ks load+mma loop.
// EPI: 0 = half: acc+bias ; 1 = half: gelu(acc+bias) ;
//      2 = float: Cout = Cin + acc + bias (Cin may equal Cout) ;
//      3 = half: acc*alpha ; 4 = half: acc
template<int EPI, bool CSKIP, bool CK>
__global__ void __launch_bounds__(128) hgemm(
    const __half* __restrict__ A, const __half* __restrict__ B,
    const float* __restrict__ bias, void* __restrict__ Cv,
    const float* __restrict__ Cin,
    int K, int lda, int ldb, int ldc,
    long long sA, long long sB, long long sC, float alpha)
{
    extern __shared__ __align__(1024) char smem[];
    const int m0 = blockIdx.y * 128;
    const int n0 = blockIdx.x * 128;
    if (CSKIP && n0 > m0 + 127) return;
    A += (long long)blockIdx.z * sA;
    B += (long long)blockIdx.z * sB;

    const int tid = threadIdx.x;
    const int lane = tid & 31;
    const int wid = tid >> 5;          // 0..3
    const int warp_m = wid & 1;        // 2 warps over M (64 rows each)
    const int warp_n = wid >> 1;       // 2 warps over N (64 cols each)
    const uint32_t sbase = smem_u32(smem);

    const int kEnd = CK ? min(K, m0 + 128) : K;
    const int ktiles = kEnd >> 6;      // chunks of 64 halves

    auto issue_tile = [&](int kt) {
        if (kt < ktiles) {
            const int k0 = kt << 6;
            const uint32_t stg = sbase + (uint32_t)(kt % NSTG) * STAGE_BYTES;
            #pragma unroll
            for (int r = 0; r < 8; r++) {
                int f = tid + (r << 7);
                int row = f >> 3, c = f & 7;           // c = 16B chunk (8 halves)
                uint32_t soff = ((uint32_t)row << 7) + ((uint32_t)(c ^ (row & 7)) << 4);
                cp_async16(stg + soff,
                           A + (long long)(m0 + row) * lda + k0 + (c << 3));
                cp_async16(stg + 16384 + soff,
                           B + (long long)(n0 + row) * ldb + k0 + (c << 3));
            }
        }
        CP_COMMIT();
    };

    float acc[4][8][4];
    #pragma unroll
    for (int i = 0; i < 4; i++)
        #pragma unroll
        for (int j = 0; j < 8; j++)
            #pragma unroll
            for (int q = 0; q < 4; q++) acc[i][j][q] = 0.f;

    const int x7 = lane & 7;
    const int aRowL = ((lane >> 3) & 1) * 8 + x7;
    const int aChunk0 = (lane >> 4);
    const int bRowL = (lane >> 4) * 8 + x7;
    const int bChunk0 = (lane >> 3) & 1;

    issue_tile(0);
    issue_tile(1);

    for (int kt = 0; kt < ktiles; kt++) {
        CP_WAIT(1);
        __syncthreads();
        issue_tile(kt + 2);

        const uint32_t stgA = sbase + (uint32_t)(kt % NSTG) * STAGE_BYTES;
        const uint32_t stgB = stgA + 16384;

        #pragma unroll
        for (int ks = 0; ks < 4; ks++) {   // each ks = k16
            uint32_t af[4][4];
            #pragma unroll
            for (int mi = 0; mi < 4; mi++) {
                int row = warp_m * 64 + mi * 16 + aRowL;
                uint32_t addr = stgA + ((uint32_t)row << 7)
                              + ((uint32_t)((ks * 2 + aChunk0) ^ x7) << 4);
                ldsm4(af[mi][0], af[mi][1], af[mi][2], af[mi][3], addr);
            }
            uint32_t bf[8][2];
            #pragma unroll
            for (int nb = 0; nb < 4; nb++) {
                int row = warp_n * 64 + nb * 16 + bRowL;
                uint32_t addr = stgB + ((uint32_t)row << 7)
                              + ((uint32_t)((ks * 2 + bChunk0) ^ x7) << 4);
                uint32_t r0, r1, r2, r3;
                ldsm4(r0, r1, r2, r3, addr);
                bf[nb * 2][0] = r0;     bf[nb * 2][1] = r1;
                bf[nb * 2 + 1][0] = r2; bf[nb * 2 + 1][1] = r3;
            }
            #pragma unroll
            for (int mi = 0; mi < 4; mi++)
                #pragma unroll
                for (int ni = 0; ni < 8; ni++)
                    mma_f16(acc[mi][ni], af[mi], bf[ni]);
        }
    }

    // ---- epilogue ----
    const int erow = lane >> 2;
    const int ecol = 2 * (lane & 3);
    #pragma unroll
    for (int mi = 0; mi < 4; mi++) {
        #pragma unroll
        for (int ni = 0; ni < 8; ni++) {
            int mbase = m0 + warp_m * 64 + mi * 16 + erow;
            int nn = n0 + warp_n * 64 + ni * 8 + ecol;
            #pragma unroll
            for (int h = 0; h < 2; h++) {
                int m = mbase + h * 8;
                float v0 = acc[mi][ni][h * 2 + 0];
                float v1 = acc[mi][ni][h * 2 + 1];
                if (EPI == 0 || EPI == 1) {
                    float2 bb = *(const float2*)(bias + nn);
                    v0 += bb.x; v1 += bb.y;
                    if (EPI == 1) {
                        v0 = 0.5f * v0 * (1.0f + erff(v0 * 0.70710678118654752f));
                        v1 = 0.5f * v1 * (1.0f + erff(v1 * 0.70710678118654752f));
                    }
                    __half* Ch = (__half*)Cv + blockIdx.z * sC;
                    *(__half2*)(Ch + (long long)m * ldc + nn) = __floats2half2_rn(v0, v1);
                } else if (EPI == 4) {
                    __half* Ch = (__half*)Cv + blockIdx.z * sC;
                    *(__half2*)(Ch + (long long)m * ldc + nn) = __floats2half2_rn(v0, v1);
                } else if (EPI == 3) {   // half: acc*alpha (scores)
                    __half* Ch = (__half*)Cv + blockIdx.z * sC;
                    *(__half2*)(Ch + (long long)m * ldc + nn) =
                        __floats2half2_rn(v0 * alpha, v1 * alpha);
                } else {   // EPI == 2: Cout = Cin + acc + bias
                    float* Cf = (float*)Cv + blockIdx.z * sC;
                    float2 bb = *(const float2*)(bias + nn);
                    float2 cv = *(const float2*)(Cin + (long long)m * ldc + nn);
                    float2 o; o.x = cv.x + v0 + bb.x; o.y = cv.y + v1 + bb.y;
                    *(float2*)(Cf + (long long)m * ldc + nn) = o;
                }
            }
        }
    }
}

// ---------------- elementwise / reductions ----------------
__device__ __forceinline__ float warpSum(float v) {
    #pragma unroll
    for (int o = 16; o > 0; o >>= 1) v += __shfl_xor_sync(0xffffffffu, v, o);
    return v;
}
__device__ __forceinline__ float warpMax(float v) {
    #pragma unroll
    for (int o = 16; o > 0; o >>= 1) v = fmaxf(v, __shfl_xor_sync(0xffffffffu, v, o));
    return v;
}
// one-shot pair reduction (sum, sumsq) across 256 threads
__device__ __forceinline__ float2 blockSum2(float a, float b) {
    __shared__ float sh[16];
    int w = threadIdx.x >> 5, l = threadIdx.x & 31;
    a = warpSum(a);
    b = warpSum(b);
    if (l == 0) { sh[w] = a; sh[w + 8] = b; }
    __syncthreads();
    float ta = 0.f, tb = 0.f;
    #pragma unroll
    for (int i = 0; i < 8; i++) { ta += sh[i]; tb += sh[i + 8]; }
    float2 r; r.x = ta; r.y = tb;
    return r;
}
__device__ __forceinline__ float blockSum(float v) {
    __shared__ float sh[8];
    int w = threadIdx.x >> 5, l = threadIdx.x & 31;
    v = warpSum(v);
    __syncthreads();
    if (l == 0) sh[w] = v;
    __syncthreads();
    float t = 0.f;
    #pragma unroll
    for (int i = 0; i < 8; i++) t += sh[i];
    return t;
}
__device__ __forceinline__ float blockMax(float v) {
    __shared__ float sh[8];
    int w = threadIdx.x >> 5, l = threadIdx.x & 31;
    v = warpMax(v);
    __syncthreads();
    if (l == 0) sh[w] = v;
    __syncthreads();
    float t = -INFINITY;
    #pragma unroll
    for (int i = 0; i < 8; i++) t = fmaxf(t, sh[i]);
    return t;
}

// convert ALL weight arrays fp32 -> fp16 in one launch
#define N4_QKV (8*3*C_*C_/4)
#define N4_OUT (8*C_*C_/4)
#define N4_FF0 (8*F_*C_/4)
#define N4_FF3 (8*C_*F_/4)
__global__ void convert_all_kernel(const float4* __restrict__ qkv_w, __half* __restrict__ wqkv,
                                   const float4* __restrict__ out_w, __half* __restrict__ wout,
                                   const float4* __restrict__ ff0_w, __half* __restrict__ wff0,
                                   const float4* __restrict__ ff3_w, __half* __restrict__ wff3)
{
    long long i = (long long)blockIdx.x * 256 + threadIdx.x;
    const float4* src; __half* dst; long long off;
    if (i < N4_QKV)                         { src = qkv_w; dst = wqkv; off = i; }
    else if (i < N4_QKV + N4_OUT)           { src = out_w; dst = wout; off = i - N4_QKV; }
    else if (i < N4_QKV + N4_OUT + N4_FF0)  { src = ff0_w; dst = wff0; off = i - N4_QKV - N4_OUT; }
    else if (i < N4_QKV + N4_OUT + N4_FF0 + N4_FF3)
                                            { src = ff3_w; dst = wff3; off = i - N4_QKV - N4_OUT - N4_FF0; }
    else return;
    float4 v = src[off];
    __half2* d2 = (__half2*)(dst + off * 4);
    d2[0] = __floats2half2_rn(v.x, v.y);
    d2[1] = __floats2half2_rn(v.z, v.w);
}

// LayerNorm, single-pass (sum, sumsq): reads fp32 src, writes fp16
__global__ void __launch_bounds__(256) ln_kernel(
    const float* __restrict__ x, const float* __restrict__ w,
    const float* __restrict__ b, __half* __restrict__ out)
{
    size_t row = blockIdx.x;
    const float4* xr = (const float4*)(x + row * C_);
    int tid = threadIdx.x;
    float4 v = xr[tid];
    float s  = v.x + v.y + v.z + v.w;
    float sq = v.x*v.x + v.y*v.y + v.z*v.z + v.w*v.w;
    float2 r = blockSum2(s, sq);
    float mean = r.x * (1.0f / C_);
    float var  = r.y * (1.0f / C_) - mean * mean;
    float inv = rsqrtf(var + 1e-5f);
    float d0 = v.x - mean, d1 = v.y - mean, d2 = v.z - mean, d3 = v.w - mean;
    float4 wv = ((const float4*)w)[tid];
    float4 bv = ((const float4*)b)[tid];
    __half2* o2 = (__half2*)(out + row * C_);
    o2[tid * 2 + 0] = __floats2half2_rn(d0 * inv * wv.x + bv.x, d1 * inv * wv.y + bv.y);
    o2[tid * 2 + 1] = __floats2half2_rn(d2 * inv * wv.z + bv.z, d3 * inv * wv.w + bv.w);
}

// causal softmax, IN PLACE on fp16 buffer (zero-filled to 128-boundary),
// FMA-pipe exp (no MUFU bottleneck)
__global__ void __launch_bounds__(256) softmax_kernel(__half* __restrict__ att)
{
    int r = blockIdx.x;
    int b = r >> 11;
    int t = r & (T_ - 1);
    __half* row = att + ((size_t)b * T_ + t) * T_;
    int n = t + 1;                        // valid entries
    int nw = (n + 127) & ~127;            // zero-fill through causal 128-boundary
    int tid = threadIdx.x;
    float vals[8];
    float vmax = -INFINITY;
    #pragma unroll
    for (int it = 0; it < 8; it++) {
        int i = tid + it * 256;
        vals[it] = (i < n) ? __half2float(row[i]) : -INFINITY;
        vmax = fmaxf(vmax, vals[it]);
    }
    vmax = blockMax(vmax);
    float s = 0.f;
    #pragma unroll
    for (int it = 0; it < 8; it++) {
        int i = tid + it * 256;
        if (i < n) { vals[it] = fexp(vals[it] - vmax); s += vals[it]; }
        else vals[it] = 0.f;
    }
    s = blockSum(s);
    float inv = 1.0f / s;
    #pragma unroll
    for (int it = 0; it < 8; it++) {
        int i = tid + it * 256;
        if (i < nw) row[i] = __float2half_rn(vals[it] * inv);
    }
}

// v[b][t][c] (inside qkv halves, offset 2C, row stride 3C) -> vt[b][c][t]
__global__ void transpose_v_kernel(const __half* __restrict__ qkv, __half* __restrict__ vt)
{
    __shared__ __half tile[32][33];
    int b = blockIdx.z;
    int t0 = blockIdx.x * 32, c0 = blockIdx.y * 32;
    int tx = threadIdx.x, ty = threadIdx.y;   // 32 x 8
    #pragma unroll
    for (int r = 0; r < 32; r += 8)
        tile[ty + r][tx] = qkv[((long long)b * T_ + t0 + ty + r) * 3 * C_ + 2 * C_ + c0 + tx];
    __syncthreads();
    #pragma unroll
    for (int r = 0; r < 32; r += 8)
        vt[((long long)b * C_ + c0 + ty + r) * T_ + t0 + tx] = tile[tx][ty + r];
}

// ---------------- host launcher ----------------
extern "C" void kernel_launch(void* const* d_in, const int* in_sizes, int n_in,
                              void* d_out, int out_size)
{
    const float* x     = (const float*)d_in[0];
    const float* ln1_w = (const float*)d_in[1];
    const float* ln1_b = (const float*)d_in[2];
    const float* qkv_w = (const float*)d_in[3];
    const float* qkv_b = (const float*)d_in[4];
    const float* out_w = (const float*)d_in[5];
    const float* out_b = (const float*)d_in[6];
    const float* ln2_w = (const float*)d_in[7];
    const float* ln2_b = (const float*)d_in[8];
    const float* ff0_w = (const float*)d_in[9];
    const float* ff0_b = (const float*)d_in[10];
    const float* ff3_w = (const float*)d_in[11];
    const float* ff3_b = (const float*)d_in[12];
    float* dout = (float*)d_out;

    float *gx;
    __half *gh, *gqkv, *gatt, *gao, *gvt, *gff;
    __half *wqkv, *wout, *wff0, *wff3;
    cudaGetSymbolAddress((void**)&gx,   g_x);
    cudaGetSymbolAddress((void**)&gh,   g_h);
    cudaGetSymbolAddress((void**)&gqkv, g_qkv);
    cudaGetSymbolAddress((void**)&gatt, g_att);
    cudaGetSymbolAddress((void**)&gao,  g_ao);
    cudaGetSymbolAddress((void**)&gvt,  g_vt);
    cudaGetSymbolAddress((void**)&gff,  g_ff);
    cudaGetSymbolAddress((void**)&wqkv, g_wqkv);
    cudaGetSymbolAddress((void**)&wout, g_wout);
    cudaGetSymbolAddress((void**)&wff0, g_wff0);
    cudaGetSymbolAddress((void**)&wff3, g_wff3);

    cudaFuncSetAttribute(hgemm<0,false,false>, cudaFuncAttributeMaxDynamicSharedMemorySize, GEMM_SMEM_BYTES);
    cudaFuncSetAttribute(hgemm<1,false,false>, cudaFuncAttributeMaxDynamicSharedMemorySize, GEMM_SMEM_BYTES);
    cudaFuncSetAttribute(hgemm<2,false,false>, cudaFuncAttributeMaxDynamicSharedMemorySize, GEMM_SMEM_BYTES);
    cudaFuncSetAttribute(hgemm<3,true,false>,  cudaFuncAttributeMaxDynamicSharedMemorySize, GEMM_SMEM_BYTES);
    cudaFuncSetAttribute(hgemm<4,false,true>,  cudaFuncAttributeMaxDynamicSharedMemorySize, GEMM_SMEM_BYTES);

    // (1) convert all weights to fp16 in ONE launch
    {
        long long total4 = (long long)N4_QKV + N4_OUT + N4_FF0 + N4_FF3;
        int blocks = (int)((total4 + 255) / 256);
        convert_all_kernel<<<blocks, 256>>>(
            (const float4*)qkv_w, wqkv,
            (const float4*)out_w, wout,
            (const float4*)ff0_w, wff0,
            (const float4*)ff3_w, wff3);
    }

    const float scale = 0.03125f;   // 1/sqrt(1024)

    for (int i = 0; i < 8; i++) {
        // residual source for this layer: x for layer 0, gx afterwards
        const float* res_in = (i == 0) ? x : gx;
        // (2) LN1 -> fp16
        ln_kernel<<<MROWS, 256>>>(res_in, ln1_w + (size_t)i * C_, ln1_b + (size_t)i * C_, gh);
        // (3) qkv = h @ qkv_w^T + qkv_b  -> fp16
        hgemm<0,false,false><<<dim3(3*C_/128, MROWS/128), 128, GEMM_SMEM_BYTES>>>(
            gh, wqkv + (size_t)i * 3 * C_ * C_, qkv_b + (size_t)i * 3 * C_, gqkv, (const float*)0,
            C_, C_, C_, 3*C_, 0, 0, 0, 1.0f);
        // (4) v^T per batch (fp16)
        transpose_v_kernel<<<dim3(T_/32, C_/32, B_), dim3(32, 8)>>>(gqkv, gvt);
        // (5) scores = (q @ k^T) * scale  -> fp16 (att buffer)
        hgemm<3,true,false><<<dim3(T_/128, T_/128, B_), 128, GEMM_SMEM_BYTES>>>(
            gqkv, gqkv + C_, (const float*)0, gatt, (const float*)0,
            C_, 3*C_, 3*C_, T_,
            (long long)T_ * 3 * C_, (long long)T_ * 3 * C_, (long long)T_ * T_, scale);
        // (6) causal softmax in place (zeros through 128-boundary)
        softmax_kernel<<<MROWS, 256>>>(gatt);
        // (7) ao = probs @ v  (NT with B=vt, K clipped) -> fp16
        hgemm<4,false,true><<<dim3(C_/128, T_/128, B_), 128, GEMM_SMEM_BYTES>>>(
            gatt, gvt, (const float*)0, gao, (const float*)0,
            T_, T_, T_, C_,
            (long long)T_ * T_, (long long)C_ * T_, (long long)T_ * C_, 1.0f);
        // (8) gx = res_in + ao @ out_w^T + out_b  (fp32 residual)
        hgemm<2,false,false><<<dim3(C_/128, MROWS/128), 128, GEMM_SMEM_BYTES>>>(
            gao, wout + (size_t)i * C_ * C_, out_b + (size_t)i * C_, gx, res_in,
            C_, C_, C_, C_, 0, 0, 0, 1.0f);
        // (9) LN2 -> fp16
        ln_kernel<<<MROWS, 256>>>(gx, ln2_w + (size_t)i * C_, ln2_b + (size_t)i * C_, gh);
        // (10) ff = gelu(h2 @ ff0_w^T + ff0_b) -> fp16
        hgemm<1,false,false><<<dim3(F_/128, MROWS/128), 128, GEMM_SMEM_BYTES>>>(
            gh, wff0 + (size_t)i * F_ * C_, ff0_b + (size_t)i * F_, gff, (const float*)0,
            C_, C_, C_, F_, 0, 0, 0, 1.0f);
        // (11) residual += ff @ ff3_w^T + ff3_b ; last layer writes d_out directly
        float* res_out = (i == 7) ? dout : gx;
        hgemm<2,false,false><<<dim3(C_/128, MROWS/128), 128, GEMM_SMEM_BYTES>>>(
            gff, wff3 + (size_t)i * C_ * F_, ff3_b + (size_t)i * C_, res_out, gx,
            F_, F_, F_, C_, 0, 0, 0, 1.0f);
    }
}

// round 15
// speedup vs baseline: 1.1509x; 1.0138x over previous
#include <cuda_runtime.h>
#include <cuda_fp16.h>
#include <math.h>
#include <stdint.h>

#define B_ 4
#define T_ 2048
#define C_ 1024
#define F_ 4096
#define MROWS (B_*T_)   // 8192

// ---------------- scratch (device globals; no allocation allowed) ----------
__device__ __align__(128) float  g_x[(size_t)MROWS*C_];        // residual (fp32)
__device__ __align__(128) __half g_h[(size_t)MROWS*C_];        // LN out
__device__ __align__(128) __half g_qkv[(size_t)MROWS*3*C_];    // q,k used; v region unused
__device__ __align__(128) __half g_att[(size_t)B_*T_*T_];      // scores -> probs (in place)
__device__ __align__(128) __half g_ao[(size_t)MROWS*C_];
__device__ __align__(128) __half g_vt[(size_t)B_*C_*T_];       // v^T per batch (written by qkv epi)
__device__ __align__(128) __half g_ff[(size_t)MROWS*F_];
// fp16 weights
__device__ __align__(128) __half g_wqkv[(size_t)8*3*C_*C_];
__device__ __align__(128) __half g_wout[(size_t)8*C_*C_];
__device__ __align__(128) __half g_wff0[(size_t)8*F_*C_];
__device__ __align__(128) __half g_wff3[(size_t)8*C_*F_];

// ================= base-target PTX helpers =================
__device__ __forceinline__ uint32_t smem_u32(const void* p) {
    uint32_t a;
    asm("{ .reg .u64 t; cvta.to.shared.u64 t, %1; cvt.u32.u64 %0, t; }" : "=r"(a) : "l"(p));
    return a;
}
__device__ __forceinline__ void cp_async16(uint32_t saddr, const void* gptr) {
    asm volatile("cp.async.cg.shared.global [%0], [%1], 16;" :: "r"(saddr), "l"(gptr) : "memory");
}
#define CP_COMMIT()  asm volatile("cp.async.commit_group;" ::: "memory")
#define CP_WAIT(n)   asm volatile("cp.async.wait_group %0;" :: "n"(n) : "memory")

__device__ __forceinline__ void ldsm4(uint32_t& r0, uint32_t& r1, uint32_t& r2, uint32_t& r3,
                                      uint32_t addr) {
    asm volatile("ldmatrix.sync.aligned.m8n8.x4.shared.b16 {%0,%1,%2,%3}, [%4];"
                 : "=r"(r0), "=r"(r1), "=r"(r2), "=r"(r3) : "r"(addr));
}
__device__ __forceinline__ void mma_f16(float* d, const uint32_t* a, const uint32_t* b) {
    asm volatile("mma.sync.aligned.m16n8k16.row.col.f32.f16.f16.f32 "
                 "{%0,%1,%2,%3}, {%4,%5,%6,%7}, {%8,%9}, {%0,%1,%2,%3};"
                 : "+f"(d[0]), "+f"(d[1]), "+f"(d[2]), "+f"(d[3])
                 : "r"(a[0]), "r"(a[1]), "r"(a[2]), "r"(a[3]), "r"(b[0]), "r"(b[1]));
}

// FMA-pipe exp: exp(x) = 2^(x*log2e), n=rint, 5-term Taylor on 2^f, |f|<=0.5.
__device__ __forceinline__ float fexp(float x) {
    x = fmaxf(x, -80.0f);
    float y = x * 1.4426950408889634f;
    float n = rintf(y);
    float f = y - n;
    float p = 1.33336e-3f;
    p = fmaf(p, f, 9.61813e-3f);
    p = fmaf(p, f, 5.5504108e-2f);
    p = fmaf(p, f, 2.4022651e-1f);
    p = fmaf(p, f, 6.9314718e-1f);
    p = fmaf(p, f, 1.0f);
    int e = (((int)n) + 127) << 23;
    return p * __int_as_float(e);
}

#define NSTG 3
#define STAGE_BYTES 32768           // 16KB A + 16KB B ; one stage = K-chunk of 64 halves
#define GEMM_SMEM_BYTES (NSTG * STAGE_BYTES)   // 96KB -> 2 CTAs/SM

// ============== fp16 mma.sync NT GEMM: D = A[M,K] * B[N,K]^T, fp32 accum ==
// CTA tile 128x128; 4 warps (2 over M x 2 over N), warp tile 64x64.
// R10/R13-proven body: burst cp.async issue after barrier, plain ks load+mma loop.
// EPI: 0 = half: acc+bias ; 1 = half: gelu(acc+bias) ;
//      2 = float: Cout = Cin + acc + bias (Cin may equal Cout) ;
//      3 = half: acc*alpha ; 4 = half: acc
// FUSEV: tiles with n0 >= 2C write acc+bias TRANSPOSED into vt (qkv fusion),
//        skipping the normal store (v region of qkv is never read).
template<int EPI, bool CSKIP, bool CK, bool FUSEV>
__global__ void __launch_bounds__(128) hgemm(
    const __half* __restrict__ A, const __half* __restrict__ B,
    const float* __restrict__ bias, void* __restrict__ Cv,
    const float* __restrict__ Cin, __half* __restrict__ vt,
    int K, int lda, int ldb, int ldc,
    long long sA, long long sB, long long sC, float alpha)
{
    extern __shared__ __align__(1024) char smem[];
    const int m0 = blockIdx.y * 128;
    const int n0 = blockIdx.x * 128;
    if (CSKIP && n0 > m0 + 127) return;
    A += (long long)blockIdx.z * sA;
    B += (long long)blockIdx.z * sB;

    const int tid = threadIdx.x;
    const int lane = tid & 31;
    const int wid = tid >> 5;          // 0..3
    const int warp_m = wid & 1;        // 2 warps over M (64 rows each)
    const int warp_n = wid >> 1;       // 2 warps over N (64 cols each)
    const uint32_t sbase = smem_u32(smem);

    const int kEnd = CK ? min(K, m0 + 128) : K;
    const int ktiles = kEnd >> 6;      // chunks of 64 halves

    auto issue_tile = [&](int kt) {
        if (kt < ktiles) {
            const int k0 = kt << 6;
            const uint32_t stg = sbase + (uint32_t)(kt % NSTG) * STAGE_BYTES;
            #pragma unroll
            for (int r = 0; r < 8; r++) {
                int f = tid + (r << 7);
                int row = f >> 3, c = f & 7;           // c = 16B chunk (8 halves)
                uint32_t soff = ((uint32_t)row << 7) + ((uint32_t)(c ^ (row & 7)) << 4);
                cp_async16(stg + soff,
                           A + (long long)(m0 + row) * lda + k0 + (c << 3));
                cp_async16(stg + 16384 + soff,
                           B + (long long)(n0 + row) * ldb + k0 + (c << 3));
            }
        }
        CP_COMMIT();
    };

    float acc[4][8][4];
    #pragma unroll
    for (int i = 0; i < 4; i++)
        #pragma unroll
        for (int j = 0; j < 8; j++)
            #pragma unroll
            for (int q = 0; q < 4; q++) acc[i][j][q] = 0.f;

    const int x7 = lane & 7;
    const int aRowL = ((lane >> 3) & 1) * 8 + x7;
    const int aChunk0 = (lane >> 4);
    const int bRowL = (lane >> 4) * 8 + x7;
    const int bChunk0 = (lane >> 3) & 1;

    issue_tile(0);
    issue_tile(1);

    for (int kt = 0; kt < ktiles; kt++) {
        CP_WAIT(1);
        __syncthreads();
        issue_tile(kt + 2);

        const uint32_t stgA = sbase + (uint32_t)(kt % NSTG) * STAGE_BYTES;
        const uint32_t stgB = stgA + 16384;

        #pragma unroll
        for (int ks = 0; ks < 4; ks++) {   // each ks = k16
            uint32_t af[4][4];
            #pragma unroll
            for (int mi = 0; mi < 4; mi++) {
                int row = warp_m * 64 + mi * 16 + aRowL;
                uint32_t addr = stgA + ((uint32_t)row << 7)
                              + ((uint32_t)((ks * 2 + aChunk0) ^ x7) << 4);
                ldsm4(af[mi][0], af[mi][1], af[mi][2], af[mi][3], addr);
            }
            uint32_t bf[8][2];
            #pragma unroll
            for (int nb = 0; nb < 4; nb++) {
                int row = warp_n * 64 + nb * 16 + bRowL;
                uint32_t addr = stgB + ((uint32_t)row << 7)
                              + ((uint32_t)((ks * 2 + bChunk0) ^ x7) << 4);
                uint32_t r0, r1, r2, r3;
                ldsm4(r0, r1, r2, r3, addr);
                bf[nb * 2][0] = r0;     bf[nb * 2][1] = r1;
                bf[nb * 2 + 1][0] = r2; bf[nb * 2 + 1][1] = r3;
            }
            #pragma unroll
            for (int mi = 0; mi < 4; mi++)
                #pragma unroll
                for (int ni = 0; ni < 8; ni++)
                    mma_f16(acc[mi][ni], af[mi], bf[ni]);
        }
    }

    // ---- epilogue ----
    const int erow = lane >> 2;
    const int ecol = 2 * (lane & 3);
    const bool vtile = FUSEV && (n0 >= 2 * C_);
    #pragma unroll
    for (int mi = 0; mi < 4; mi++) {
        #pragma unroll
        for (int ni = 0; ni < 8; ni++) {
            int mbase = m0 + warp_m * 64 + mi * 16 + erow;
            int nn = n0 + warp_n * 64 + ni * 8 + ecol;
            #pragma unroll
            for (int h = 0; h < 2; h++) {
                int m = mbase + h * 8;
                float v0 = acc[mi][ni][h * 2 + 0];
                float v1 = acc[mi][ni][h * 2 + 1];
                if (EPI == 0 || EPI == 1) {
                    float2 bb = *(const float2*)(bias + nn);
                    v0 += bb.x; v1 += bb.y;
                    if (EPI == 1) {
                        v0 = 0.5f * v0 * (1.0f + erff(v0 * 0.70710678118654752f));
                        v1 = 0.5f * v1 * (1.0f + erff(v1 * 0.70710678118654752f));
                    }
                    __half2 hv = __floats2half2_rn(v0, v1);
                    if (vtile) {
                        // write v transposed: vt[b][c][t], c = nn-2C, t = m & (T-1)
                        int c = nn - 2 * C_;
                        int bz = m >> 11;
                        int tl = m & (T_ - 1);
                        __half* vp = vt + ((size_t)bz * C_ + c) * T_ + tl;
                        vp[0]  = __low2half(hv);
                        vp[T_] = __high2half(hv);   // channel c+1
                    } else {
                        __half* Ch = (__half*)Cv + blockIdx.z * sC;
                        *(__half2*)(Ch + (long long)m * ldc + nn) = hv;
                    }
                } else if (EPI == 4) {
                    __half* Ch = (__half*)Cv + blockIdx.z * sC;
                    *(__half2*)(Ch + (long long)m * ldc + nn) = __floats2half2_rn(v0, v1);
                } else if (EPI == 3) {   // half: acc*alpha (scores)
                    __half* Ch = (__half*)Cv + blockIdx.z * sC;
                    *(__half2*)(Ch + (long long)m * ldc + nn) =
                        __floats2half2_rn(v0 * alpha, v1 * alpha);
                } else {   // EPI == 2: Cout = Cin + acc + bias
                    float* Cf = (float*)Cv + blockIdx.z * sC;
                    float2 bb = *(const float2*)(bias + nn);
                    float2 cv = *(const float2*)(Cin + (long long)m * ldc + nn);
                    float2 o; o.x = cv.x + v0 + bb.x; o.y = cv.y + v1 + bb.y;
                    *(float2*)(Cf + (long long)m * ldc + nn) = o;
                }
            }
        }
    }
}

// ---------------- elementwise / reductions ----------------
__device__ __forceinline__ float warpSum(float v) {
    #pragma unroll
    for (int o = 16; o > 0; o >>= 1) v += __shfl_xor_sync(0xffffffffu, v, o);
    return v;
}
__device__ __forceinline__ float warpMax(float v) {
    #pragma unroll
    for (int o = 16; o > 0; o >>= 1) v = fmaxf(v, __shfl_xor_sync(0xffffffffu, v, o));
    return v;
}
// one-shot pair reduction (sum, sumsq) across 256 threads
__device__ __forceinline__ float2 blockSum2(float a, float b) {
    __shared__ float sh[16];
    int w = threadIdx.x >> 5, l = threadIdx.x & 31;
    a = warpSum(a);
    b = warpSum(b);
    if (l == 0) { sh[w] = a; sh[w + 8] = b; }
    __syncthreads();
    float ta = 0.f, tb = 0.f;
    #pragma unroll
    for (int i = 0; i < 8; i++) { ta += sh[i]; tb += sh[i + 8]; }
    float2 r; r.x = ta; r.y = tb;
    return r;
}
__device__ __forceinline__ float blockSum(float v) {
    __shared__ float sh[8];
    int w = threadIdx.x >> 5, l = threadIdx.x & 31;
    v = warpSum(v);
    __syncthreads();
    if (l == 0) sh[w] = v;
    __syncthreads();
    float t = 0.f;
    #pragma unroll
    for (int i = 0; i < 8; i++) t += sh[i];
    return t;
}
__device__ __forceinline__ float blockMax(float v) {
    __shared__ float sh[8];
    int w = threadIdx.x >> 5, l = threadIdx.x & 31;
    v = warpMax(v);
    __syncthreads();
    if (l == 0) sh[w] = v;
    __syncthreads();
    float t = -INFINITY;
    #pragma unroll
    for (int i = 0; i < 8; i++) t = fmaxf(t, sh[i]);
    return t;
}

// convert ALL weight arrays fp32 -> fp16 in one launch
#define N4_QKV (8*3*C_*C_/4)
#define N4_OUT (8*C_*C_/4)
#define N4_FF0 (8*F_*C_/4)
#define N4_FF3 (8*C_*F_/4)
__global__ void convert_all_kernel(const float4* __restrict__ qkv_w, __half* __restrict__ wqkv,
                                   const float4* __restrict__ out_w, __half* __restrict__ wout,
                                   const float4* __restrict__ ff0_w, __half* __restrict__ wff0,
                                   const float4* __restrict__ ff3_w, __half* __restrict__ wff3)
{
    long long i = (long long)blockIdx.x * 256 + threadIdx.x;
    const float4* src; __half* dst; long long off;
    if (i < N4_QKV)                         { src = qkv_w; dst = wqkv; off = i; }
    else if (i < N4_QKV + N4_OUT)           { src = out_w; dst = wout; off = i - N4_QKV; }
    else if (i < N4_QKV + N4_OUT + N4_FF0)  { src = ff0_w; dst = wff0; off = i - N4_QKV - N4_OUT; }
    else if (i < N4_QKV + N4_OUT + N4_FF0 + N4_FF3)
                                            { src = ff3_w; dst = wff3; off = i - N4_QKV - N4_OUT - N4_FF0; }
    else return;
    float4 v = src[off];
    __half2* d2 = (__half2*)(dst + off * 4);
    d2[0] = __floats2half2_rn(v.x, v.y);
    d2[1] = __floats2half2_rn(v.z, v.w);
}

// LayerNorm, single-pass (sum, sumsq): reads fp32 src, writes fp16
__global__ void __launch_bounds__(256) ln_kernel(
    const float* __restrict__ x, const float* __restrict__ w,
    const float* __restrict__ b, __half* __restrict__ out)
{
    size_t row = blockIdx.x;
    const float4* xr = (const float4*)(x + row * C_);
    int tid = threadIdx.x;
    float4 v = xr[tid];
    float s  = v.x + v.y + v.z + v.w;
    float sq = v.x*v.x + v.y*v.y + v.z*v.z + v.w*v.w;
    float2 r = blockSum2(s, sq);
    float mean = r.x * (1.0f / C_);
    float var  = r.y * (1.0f / C_) - mean * mean;
    float inv = rsqrtf(var + 1e-5f);
    float d0 = v.x - mean, d1 = v.y - mean, d2 = v.z - mean, d3 = v.w - mean;
    float4 wv = ((const float4*)w)[tid];
    float4 bv = ((const float4*)b)[tid];
    __half2* o2 = (__half2*)(out + row * C_);
    o2[tid * 2 + 0] = __floats2half2_rn(d0 * inv * wv.x + bv.x, d1 * inv * wv.y + bv.y);
    o2[tid * 2 + 1] = __floats2half2_rn(d2 * inv * wv.z + bv.z, d3 * inv * wv.w + bv.w);
}

// causal softmax, IN PLACE on fp16 buffer (zero-filled to 128-boundary),
// FMA-pipe exp (no MUFU bottleneck)
__global__ void __launch_bounds__(256) softmax_kernel(__half* __restrict__ att)
{
    int r = blockIdx.x;
    int b = r >> 11;
    int t = r & (T_ - 1);
    __half* row = att + ((size_t)b * T_ + t) * T_;
    int n = t + 1;                        // valid entries
    int nw = (n + 127) & ~127;            // zero-fill through causal 128-boundary
    int tid = threadIdx.x;
    float vals[8];
    float vmax = -INFINITY;
    #pragma unroll
    for (int it = 0; it < 8; it++) {
        int i = tid + it * 256;
        vals[it] = (i < n) ? __half2float(row[i]) : -INFINITY;
        vmax = fmaxf(vmax, vals[it]);
    }
    vmax = blockMax(vmax);
    float s = 0.f;
    #pragma unroll
    for (int it = 0; it < 8; it++) {
        int i = tid + it * 256;
        if (i < n) { vals[it] = fexp(vals[it] - vmax); s += vals[it]; }
        else vals[it] = 0.f;
    }
    s = blockSum(s);
    float inv = 1.0f / s;
    #pragma unroll
    for (int it = 0; it < 8; it++) {
        int i = tid + it * 256;
        if (i < nw) row[i] = __float2half_rn(vals[it] * inv);
    }
}

// ---------------- host launcher ----------------
extern "C" void kernel_launch(void* const* d_in, const int* in_sizes, int n_in,
                              void* d_out, int out_size)
{
    const float* x     = (const float*)d_in[0];
    const float* ln1_w = (const float*)d_in[1];
    const float* ln1_b = (const float*)d_in[2];
    const float* qkv_w = (const float*)d_in[3];
    const float* qkv_b = (const float*)d_in[4];
    const float* out_w = (const float*)d_in[5];
    const float* out_b = (const float*)d_in[6];
    const float* ln2_w = (const float*)d_in[7];
    const float* ln2_b = (const float*)d_in[8];
    const float* ff0_w = (const float*)d_in[9];
    const float* ff0_b = (const float*)d_in[10];
    const float* ff3_w = (const float*)d_in[11];
    const float* ff3_b = (const float*)d_in[12];
    float* dout = (float*)d_out;

    float *gx;
    __half *gh, *gqkv, *gatt, *gao, *gvt, *gff;
    __half *wqkv, *wout, *wff0, *wff3;
    cudaGetSymbolAddress((void**)&gx,   g_x);
    cudaGetSymbolAddress((void**)&gh,   g_h);
    cudaGetSymbolAddress((void**)&gqkv, g_qkv);
    cudaGetSymbolAddress((void**)&gatt, g_att);
    cudaGetSymbolAddress((void**)&gao,  g_ao);
    cudaGetSymbolAddress((void**)&gvt,  g_vt);
    cudaGetSymbolAddress((void**)&gff,  g_ff);
    cudaGetSymbolAddress((void**)&wqkv, g_wqkv);
    cudaGetSymbolAddress((void**)&wout, g_wout);
    cudaGetSymbolAddress((void**)&wff0, g_wff0);
    cudaGetSymbolAddress((void**)&wff3, g_wff3);

    cudaFuncSetAttribute(hgemm<0,false,false,true>,  cudaFuncAttributeMaxDynamicSharedMemorySize, GEMM_SMEM_BYTES);
    cudaFuncSetAttribute(hgemm<1,false,false,false>, cudaFuncAttributeMaxDynamicSharedMemorySize, GEMM_SMEM_BYTES);
    cudaFuncSetAttribute(hgemm<2,false,false,false>, cudaFuncAttributeMaxDynamicSharedMemorySize, GEMM_SMEM_BYTES);
    cudaFuncSetAttribute(hgemm<3,true,false,false>,  cudaFuncAttributeMaxDynamicSharedMemorySize, GEMM_SMEM_BYTES);
    cudaFuncSetAttribute(hgemm<4,false,true,false>,  cudaFuncAttributeMaxDynamicSharedMemorySize, GEMM_SMEM_BYTES);

    // (1) convert all weights to fp16 in ONE launch
    {
        long long total4 = (long long)N4_QKV + N4_OUT + N4_FF0 + N4_FF3;
        int blocks = (int)((total4 + 255) / 256);
        convert_all_kernel<<<blocks, 256>>>(
            (const float4*)qkv_w, wqkv,
            (const float4*)out_w, wout,
            (const float4*)ff0_w, wff0,
            (const float4*)ff3_w, wff3);
    }

    const float scale = 0.03125f;   // 1/sqrt(1024)

    for (int i = 0; i < 8; i++) {
        // residual source for this layer: x for layer 0, gx afterwards
        const float* res_in = (i == 0) ? x : gx;
        // (2) LN1 -> fp16
        ln_kernel<<<MROWS, 256>>>(res_in, ln1_w + (size_t)i * C_, ln1_b + (size_t)i * C_, gh);
        // (3) qkv = h @ qkv_w^T + qkv_b ; v tiles written transposed into gvt
        hgemm<0,false,false,true><<<dim3(3*C_/128, MROWS/128), 128, GEMM_SMEM_BYTES>>>(
            gh, wqkv + (size_t)i * 3 * C_ * C_, qkv_b + (size_t)i * 3 * C_, gqkv, (const float*)0, gvt,
            C_, C_, C_, 3*C_, 0, 0, 0, 1.0f);
        // (4) scores = (q @ k^T) * scale  -> fp16 (att buffer)
        hgemm<3,true,false,false><<<dim3(T_/128, T_/128, B_), 128, GEMM_SMEM_BYTES>>>(
            gqkv, gqkv + C_, (const float*)0, gatt, (const float*)0, (__half*)0,
            C_, 3*C_, 3*C_, T_,
            (long long)T_ * 3 * C_, (long long)T_ * 3 * C_, (long long)T_ * T_, scale);
        // (5) causal softmax in place (zeros through 128-boundary)
        softmax_kernel<<<MROWS, 256>>>(gatt);
        // (6) ao = probs @ v  (NT with B=vt, K clipped) -> fp16
        hgemm<4,false,true,false><<<dim3(C_/128, T_/128, B_), 128, GEMM_SMEM_BYTES>>>(
            gatt, gvt, (const float*)0, gao, (const float*)0, (__half*)0,
            T_, T_, T_, C_,
            (long long)T_ * T_, (long long)C_ * T_, (long long)T_ * C_, 1.0f);
        // (7) gx = res_in + ao @ out_w^T + out_b  (fp32 residual)
        hgemm<2,false,false,false><<<dim3(C_/128, MROWS/128), 128, GEMM_SMEM_BYTES>>>(
            gao, wout + (size_t)i * C_ * C_, out_b + (size_t)i * C_, gx, res_in, (__half*)0,
            C_, C_, C_, C_, 0, 0, 0, 1.0f);
        // (8) LN2 -> fp16
        ln_kernel<<<MROWS, 256>>>(gx, ln2_w + (size_t)i * C_, ln2_b + (size_t)i * C_, gh);
        // (9) ff = gelu(h2 @ ff0_w^T + ff0_b) -> fp16
        hgemm<1,false,false,false><<<dim3(F_/128, MROWS/128), 128, GEMM_SMEM_BYTES>>>(
            gh, wff0 + (size_t)i * F_ * C_, ff0_b + (size_t)i * F_, gff, (const float*)0, (__half*)0,
            C_, C_, C_, F_, 0, 0, 0, 1.0f);
        // (10) residual += ff @ ff3_w^T + ff3_b ; last layer writes d_out directly
        float* res_out = (i == 7) ? dout : gx;
        hgemm<2,false,false,false><<<dim3(C_/128, MROWS/128), 128, GEMM_SMEM_BYTES>>>(
            gff, wff3 + (size_t)i * C_ * F_, ff3_b + (size_t)i * C_, res_out, gx, (__half*)0,
            F_, F_, F_, C_, 0, 0, 0, 1.0f);
    }
}